// round 1
// baseline (speedup 1.0000x reference)
#include <cuda_runtime.h>

#define N_NODES 32000
#define N_EDGES 512000
#define LATENT 32
#define HID 128
#define HSTR 132          // padded hidden row stride (floats) to dodge bank conflicts

// ---------------- persistent scratch (device globals; no allocation) ----------------
__device__ float g_node[N_NODES * LATENT];
__device__ float g_edge[N_EDGES * LATENT];
__device__ float g_agg [N_NODES * LATENT];

// ---------------- packed f32x2 helpers ----------------
__device__ __forceinline__ unsigned long long pack2(float lo, float hi) {
    unsigned long long r;
    asm("mov.b64 %0, {%1, %2};" : "=l"(r) : "r"(__float_as_uint(lo)), "r"(__float_as_uint(hi)));
    return r;
}
__device__ __forceinline__ unsigned long long fma2(unsigned long long a, unsigned long long b,
                                                   unsigned long long c) {
    unsigned long long d;
    asm("fma.rn.f32x2 %0, %1, %2, %3;" : "=l"(d) : "l"(a), "l"(b), "l"(c));
    return d;
}
__device__ __forceinline__ float2 unpack2(unsigned long long v) {
    unsigned int lo, hi;
    asm("mov.b64 {%0, %1}, %2;" : "=r"(lo), "=r"(hi) : "l"(v));
    return make_float2(__uint_as_float(lo), __uint_as_float(hi));
}
__device__ __forceinline__ float f4c(const float4& v, int i) {
    return i == 0 ? v.x : (i == 1 ? v.y : (i == 2 ? v.z : v.w));
}

// ---------------- GEMM layer: [32 x K] @ [K x 128] -> relu -> smem [32 x HSTR] ----------------
// 128 threads: thread = (rowg = tid>>4 -> 4 rows, colg = tid&15 -> 8 cols)
// Accumulators: 16 f32x2 pairs = 4 rows x 8 cols.
template<int K, int XSTR, bool VEC>
__device__ __forceinline__ void layer128(const float* __restrict__ Xs,
                                         const float* __restrict__ W,
                                         float* __restrict__ Out, int tid) {
    const int r0 = (tid >> 4) * 4;
    const int c0 = (tid & 15) * 8;
    unsigned long long acc[16];
#pragma unroll
    for (int i = 0; i < 16; i++) acc[i] = 0ull;

    if (VEC) {
#pragma unroll 2
        for (int k4 = 0; k4 < K / 4; k4++) {
            float4 a0 = *(const float4*)(Xs + (r0 + 0) * XSTR + k4 * 4);
            float4 a1 = *(const float4*)(Xs + (r0 + 1) * XSTR + k4 * 4);
            float4 a2 = *(const float4*)(Xs + (r0 + 2) * XSTR + k4 * 4);
            float4 a3 = *(const float4*)(Xs + (r0 + 3) * XSTR + k4 * 4);
#pragma unroll
            for (int kk = 0; kk < 4; kk++) {
                const float* wr = W + (k4 * 4 + kk) * HID + c0;
                ulonglong2 wA = *(const ulonglong2*)(wr);
                ulonglong2 wB = *(const ulonglong2*)(wr + 4);
                unsigned long long p0 = pack2(f4c(a0, kk), f4c(a0, kk));
                unsigned long long p1 = pack2(f4c(a1, kk), f4c(a1, kk));
                unsigned long long p2 = pack2(f4c(a2, kk), f4c(a2, kk));
                unsigned long long p3 = pack2(f4c(a3, kk), f4c(a3, kk));
                acc[0]  = fma2(p0, wA.x, acc[0]);  acc[1]  = fma2(p0, wA.y, acc[1]);
                acc[2]  = fma2(p0, wB.x, acc[2]);  acc[3]  = fma2(p0, wB.y, acc[3]);
                acc[4]  = fma2(p1, wA.x, acc[4]);  acc[5]  = fma2(p1, wA.y, acc[5]);
                acc[6]  = fma2(p1, wB.x, acc[6]);  acc[7]  = fma2(p1, wB.y, acc[7]);
                acc[8]  = fma2(p2, wA.x, acc[8]);  acc[9]  = fma2(p2, wA.y, acc[9]);
                acc[10] = fma2(p2, wB.x, acc[10]); acc[11] = fma2(p2, wB.y, acc[11]);
                acc[12] = fma2(p3, wA.x, acc[12]); acc[13] = fma2(p3, wA.y, acc[13]);
                acc[14] = fma2(p3, wB.x, acc[14]); acc[15] = fma2(p3, wB.y, acc[15]);
            }
        }
    } else {
#pragma unroll
        for (int k = 0; k < K; k++) {
            float a0 = Xs[(r0 + 0) * XSTR + k];
            float a1 = Xs[(r0 + 1) * XSTR + k];
            float a2 = Xs[(r0 + 2) * XSTR + k];
            float a3 = Xs[(r0 + 3) * XSTR + k];
            const float* wr = W + k * HID + c0;
            ulonglong2 wA = *(const ulonglong2*)(wr);
            ulonglong2 wB = *(const ulonglong2*)(wr + 4);
            unsigned long long p0 = pack2(a0, a0);
            unsigned long long p1 = pack2(a1, a1);
            unsigned long long p2 = pack2(a2, a2);
            unsigned long long p3 = pack2(a3, a3);
            acc[0]  = fma2(p0, wA.x, acc[0]);  acc[1]  = fma2(p0, wA.y, acc[1]);
            acc[2]  = fma2(p0, wB.x, acc[2]);  acc[3]  = fma2(p0, wB.y, acc[3]);
            acc[4]  = fma2(p1, wA.x, acc[4]);  acc[5]  = fma2(p1, wA.y, acc[5]);
            acc[6]  = fma2(p1, wB.x, acc[6]);  acc[7]  = fma2(p1, wB.y, acc[7]);
            acc[8]  = fma2(p2, wA.x, acc[8]);  acc[9]  = fma2(p2, wA.y, acc[9]);
            acc[10] = fma2(p2, wB.x, acc[10]); acc[11] = fma2(p2, wB.y, acc[11]);
            acc[12] = fma2(p3, wA.x, acc[12]); acc[13] = fma2(p3, wA.y, acc[13]);
            acc[14] = fma2(p3, wB.x, acc[14]); acc[15] = fma2(p3, wB.y, acc[15]);
        }
    }
    // relu + store
#pragma unroll
    for (int r = 0; r < 4; r++) {
        float2 v0 = unpack2(acc[r * 4 + 0]);
        float2 v1 = unpack2(acc[r * 4 + 1]);
        float2 v2 = unpack2(acc[r * 4 + 2]);
        float2 v3 = unpack2(acc[r * 4 + 3]);
        float4 o0 = make_float4(fmaxf(v0.x, 0.f), fmaxf(v0.y, 0.f), fmaxf(v1.x, 0.f), fmaxf(v1.y, 0.f));
        float4 o1 = make_float4(fmaxf(v2.x, 0.f), fmaxf(v2.y, 0.f), fmaxf(v3.x, 0.f), fmaxf(v3.y, 0.f));
        *(float4*)(Out + (r0 + r) * HSTR + c0)     = o0;
        *(float4*)(Out + (r0 + r) * HSTR + c0 + 4) = o1;
    }
}

// ---------------- last layer: [32 x 128] @ [128 x 32] -> out (no relu) ----------------
// thread = (row = tid>>2, 8 cols at (tid&3)*8)
__device__ __forceinline__ void layer_out32(const float* __restrict__ Hs,
                                            const float* __restrict__ W,
                                            float out[8], int tid) {
    const int row = tid >> 2;
    const int c0  = (tid & 3) * 8;
    unsigned long long acc[4] = {0ull, 0ull, 0ull, 0ull};
#pragma unroll 4
    for (int k4 = 0; k4 < HID / 4; k4++) {
        float4 a = *(const float4*)(Hs + row * HSTR + k4 * 4);
#pragma unroll
        for (int kk = 0; kk < 4; kk++) {
            const float* wr = W + (k4 * 4 + kk) * 32 + c0;
            ulonglong2 wA = *(const ulonglong2*)(wr);
            ulonglong2 wB = *(const ulonglong2*)(wr + 4);
            unsigned long long ap = pack2(f4c(a, kk), f4c(a, kk));
            acc[0] = fma2(ap, wA.x, acc[0]);
            acc[1] = fma2(ap, wA.y, acc[1]);
            acc[2] = fma2(ap, wB.x, acc[2]);
            acc[3] = fma2(ap, wB.y, acc[3]);
        }
    }
#pragma unroll
    for (int p = 0; p < 4; p++) {
        float2 v = unpack2(acc[p]);
        out[p * 2 + 0] = v.x;
        out[p * 2 + 1] = v.y;
    }
}

// ---------------- encoder: in[rows x IN] -> MLP(IN->128->128->32) -> dst ----------------
template<int DST>  // 0 = g_node, 1 = g_edge
__global__ void __launch_bounds__(128) enc_kernel(const float* __restrict__ in,
                                                  const float* __restrict__ w0,
                                                  const float* __restrict__ w1,
                                                  const float* __restrict__ w2) {
    __shared__ float Xs[32][4];
    __shared__ float H1[32][HSTR];
    __shared__ float H2[32][HSTR];
    const int tid = threadIdx.x;
    const int b0  = blockIdx.x * 32;
    if (tid < 96) {
        int row = tid / 3, c = tid % 3;
        Xs[row][c] = in[(b0 + row) * 3 + c];
    }
    __syncthreads();
    layer128<3, 4, false>(&Xs[0][0], w0, &H1[0][0], tid);
    __syncthreads();
    layer128<128, HSTR, true>(&H1[0][0], w1, &H2[0][0], tid);
    __syncthreads();
    float out[8];
    layer_out32(&H2[0][0], w2, out, tid);
    const int row = tid >> 2, c0 = (tid & 3) * 8;
    float* dst = (DST == 0 ? g_node : g_edge);
    float4 o0 = make_float4(out[0], out[1], out[2], out[3]);
    float4 o1 = make_float4(out[4], out[5], out[6], out[7]);
    *(float4*)(dst + (b0 + row) * LATENT + c0)     = o0;
    *(float4*)(dst + (b0 + row) * LATENT + c0 + 4) = o1;
}

// ---------------- edge update: e_in=[edge|node[s]|node[r]] -> MLP(96->128->128->32)+res,
// plus fused segment_sum scatter into g_agg ----------------
__global__ void __launch_bounds__(128) edge_kernel(const int* __restrict__ gi,
                                                   const float* __restrict__ w0,
                                                   const float* __restrict__ w1,
                                                   const float* __restrict__ w2) {
    __shared__ float Xs[32][100];
    __shared__ float H1[32][HSTR];
    __shared__ float H2[32][HSTR];
    __shared__ int   sidx[32][2];
    const int tid = threadIdx.x;
    const int e0  = blockIdx.x * 32;
    if (tid < 64) sidx[tid >> 1][tid & 1] = gi[(e0 + (tid >> 1)) * 2 + (tid & 1)];
    __syncthreads();
    {
        const int row = tid >> 2, j = tid & 3;
        const int e = e0 + row, s = sidx[row][0], r = sidx[row][1];
#pragma unroll
        for (int p = 0; p < 6; p++) {
            int col = (j + p * 4) * 4;  // 0..92
            float4 v;
            if (col < 32)      v = *(const float4*)(g_edge + e * LATENT + col);
            else if (col < 64) v = *(const float4*)(g_node + s * LATENT + (col - 32));
            else               v = *(const float4*)(g_node + r * LATENT + (col - 64));
            *(float4*)(&Xs[row][col]) = v;
        }
    }
    __syncthreads();
    layer128<96, 100, true>(&Xs[0][0], w0, &H1[0][0], tid);
    __syncthreads();
    layer128<128, HSTR, true>(&H1[0][0], w1, &H2[0][0], tid);
    __syncthreads();
    float out[8];
    layer_out32(&H2[0][0], w2, out, tid);
    const int row = tid >> 2, c0 = (tid & 3) * 8;
    const int e = e0 + row, rcv = sidx[row][1];
    float v[8];
#pragma unroll
    for (int j = 0; j < 8; j++) v[j] = out[j] + Xs[row][c0 + j];  // residual
    *(float4*)(g_edge + e * LATENT + c0)     = make_float4(v[0], v[1], v[2], v[3]);
    *(float4*)(g_edge + e * LATENT + c0 + 4) = make_float4(v[4], v[5], v[6], v[7]);
#pragma unroll
    for (int j = 0; j < 8; j++) atomicAdd(&g_agg[rcv * LATENT + c0 + j], v[j]);
}

// ---------------- node update: n_in=[node|agg] -> MLP(64->128->128->32)+res ----------------
__global__ void __launch_bounds__(128) node_kernel(const float* __restrict__ w0,
                                                   const float* __restrict__ w1,
                                                   const float* __restrict__ w2) {
    __shared__ float Xs[32][68];
    __shared__ float H1[32][HSTR];
    __shared__ float H2[32][HSTR];
    const int tid = threadIdx.x;
    const int n0  = blockIdx.x * 32;
    {
        const int row = tid >> 2, j = tid & 3;
        const int n = n0 + row;
#pragma unroll
        for (int p = 0; p < 4; p++) {
            int col = (j + p * 4) * 4;  // 0..60
            float4 v;
            if (col < 32) v = *(const float4*)(g_node + n * LATENT + col);
            else          v = *(const float4*)(g_agg  + n * LATENT + (col - 32));
            *(float4*)(&Xs[row][col]) = v;
        }
    }
    __syncthreads();
    layer128<64, 68, true>(&Xs[0][0], w0, &H1[0][0], tid);
    __syncthreads();
    layer128<128, HSTR, true>(&H1[0][0], w1, &H2[0][0], tid);
    __syncthreads();
    float out[8];
    layer_out32(&H2[0][0], w2, out, tid);
    const int row = tid >> 2, c0 = (tid & 3) * 8;
    const int n = n0 + row;
    float v[8];
#pragma unroll
    for (int j = 0; j < 8; j++) v[j] = out[j] + Xs[row][c0 + j];
    *(float4*)(g_node + n * LATENT + c0)     = make_float4(v[0], v[1], v[2], v[3]);
    *(float4*)(g_node + n * LATENT + c0 + 4) = make_float4(v[4], v[5], v[6], v[7]);
}

// ---------------- decoder: node -> MLP(32->128->128->1) ----------------
__global__ void __launch_bounds__(128) dec_kernel(const float* __restrict__ w0,
                                                  const float* __restrict__ w1,
                                                  const float* __restrict__ w2,
                                                  float* __restrict__ out) {
    __shared__ float Xs[32][36];
    __shared__ float H1[32][HSTR];
    __shared__ float H2[32][HSTR];
    const int tid = threadIdx.x;
    const int b0  = blockIdx.x * 32;
    {
        const int row = tid >> 2, j = tid & 3;
#pragma unroll
        for (int p = 0; p < 2; p++) {
            int col = (j + p * 4) * 4;  // 0..28
            *(float4*)(&Xs[row][col]) = *(const float4*)(g_node + (b0 + row) * LATENT + col);
        }
    }
    __syncthreads();
    layer128<32, 36, true>(&Xs[0][0], w0, &H1[0][0], tid);
    __syncthreads();
    layer128<128, HSTR, true>(&H1[0][0], w1, &H2[0][0], tid);
    __syncthreads();
    if (tid < 32) {
        float acc = 0.f;
#pragma unroll 8
        for (int k4 = 0; k4 < HID / 4; k4++) {
            float4 a = *(const float4*)(&H2[tid][k4 * 4]);
            float4 w = *(const float4*)(w2 + k4 * 4);   // dec_w2 is [128,1] = contiguous 128
            acc = fmaf(a.x, w.x, acc);
            acc = fmaf(a.y, w.y, acc);
            acc = fmaf(a.z, w.z, acc);
            acc = fmaf(a.w, w.w, acc);
        }
        out[b0 + tid] = acc;
    }
}

__global__ void zero_agg_kernel() {
    int i = blockIdx.x * 256 + threadIdx.x;           // 1000 x 256 = 256000 float4 = 1.024M floats
    ((float4*)g_agg)[i] = make_float4(0.f, 0.f, 0.f, 0.f);
}

// ---------------- launch ----------------
extern "C" void kernel_launch(void* const* d_in, const int* in_sizes, int n_in,
                              void* d_out, int out_size) {
    const float* input_node = (const float*)d_in[0];
    const float* input_edge = (const float*)d_in[1];
    const int*   gi         = (const int*)d_in[2];
    const float* enc_n_w0 = (const float*)d_in[3];
    const float* enc_n_w1 = (const float*)d_in[4];
    const float* enc_n_w2 = (const float*)d_in[5];
    const float* enc_e_w0 = (const float*)d_in[6];
    const float* enc_e_w1 = (const float*)d_in[7];
    const float* enc_e_w2 = (const float*)d_in[8];
    const float* ep_w0 = (const float*)d_in[9];
    const float* ep_w1 = (const float*)d_in[10];
    const float* ep_w2 = (const float*)d_in[11];
    const float* np_w0 = (const float*)d_in[12];
    const float* np_w1 = (const float*)d_in[13];
    const float* np_w2 = (const float*)d_in[14];
    const float* dec_w0 = (const float*)d_in[15];
    const float* dec_w1 = (const float*)d_in[16];
    const float* dec_w2 = (const float*)d_in[17];
    float* out = (float*)d_out;

    enc_kernel<0><<<N_NODES / 32, 128>>>(input_node, enc_n_w0, enc_n_w1, enc_n_w2);
    enc_kernel<1><<<N_EDGES / 32, 128>>>(input_edge, enc_e_w0, enc_e_w1, enc_e_w2);

    for (int it = 0; it < 4; it++) {
        zero_agg_kernel<<<N_NODES * LATENT / 4 / 256, 256>>>();
        edge_kernel<<<N_EDGES / 32, 128>>>(gi,
                                           ep_w0 + it * 96 * 128,
                                           ep_w1 + it * 128 * 128,
                                           ep_w2 + it * 128 * 32);
        node_kernel<<<N_NODES / 32, 128>>>(np_w0 + it * 64 * 128,
                                           np_w1 + it * 128 * 128,
                                           np_w2 + it * 128 * 32);
    }
    dec_kernel<<<N_NODES / 32, 128>>>(dec_w0, dec_w1, dec_w2, out);
}